// round 14
// baseline (speedup 1.0000x reference)
#include <cuda_runtime.h>
#include <cuda_fp16.h>
#include <cstdint>

// ---------------- problem constants ----------------
#define C_IN   256
#define C_OUT  256
#define HW     4096
#define KTAPS  9
#define KTOT   2304          // tap-major: kord = tap*256 + c
#define MTOT   16384

// ---------------- GEMM tiling ----------------
#define BM 64
#define BN 128
#define BK 64
#define NCHUNK 36            // KTOT/BK
#define NTHREADS 128

#define PITCH 144            // 64 k * 2B + 16B pad (conflict-free)
#define ABUF  (BM * PITCH)   // 9216
#define BBUF  (BN * PITCH)   // 18432
#define STAGE (ABUF + BBUF)  // 27648
#define GA  0
#define GB  ABUF
#define GSMEM (2 * STAGE)    // 55296 -> 4 CTAs/SM

#define CS_PITCH 65

// ---------------- device scratch ----------------
__device__ float    g_xT[4 * HW * C_IN];                  // NHWC, 16MB
__device__ __align__(16) uint16_t g_wBf[C_OUT * KTOT];    // fp16, [o][kord]
__device__ __align__(16) uint16_t g_Af[(size_t)MTOT * KTOT];  // im2col fp16

// ---------------- prep kernels ----------------
__global__ void prep_w(const float* __restrict__ w) {
    int i = blockIdx.x * 256 + threadIdx.x;
    int kord = i % KTOT;
    int o    = i / KTOT;
    int tap  = kord >> 8;
    int c    = kord & 255;
    __half h = __float2half_rn(w[o * KTOT + c * KTAPS + tap]);
    g_wBf[i] = *(uint16_t*)&h;
}

__global__ void transpose_x(const float* __restrict__ x) {
    __shared__ float t[32][33];
    const int b   = blockIdx.z;
    const int hw0 = blockIdx.x * 32;
    const int c0  = blockIdx.y * 32;
    const int tx  = threadIdx.x, ty = threadIdx.y;
    #pragma unroll
    for (int i = 0; i < 4; ++i)
        t[ty + i * 8][tx] = x[((b * C_IN + c0 + ty + i * 8) << 12) + hw0 + tx];
    __syncthreads();
    #pragma unroll
    for (int i = 0; i < 4; ++i)
        g_xT[b * (HW * C_IN) + (hw0 + ty + i * 8) * C_IN + c0 + tx] =
            t[tx][ty + i * 8];
}

// ---------------- im2col -> single fp16 (no smem, no syncs) ----------------
__global__ __launch_bounds__(256)
void im2col_f16(const float* __restrict__ off)
{
    const int tid = threadIdx.x;
    const int pos = tid >> 3;
    const int sub = tid & 7;
    const int m   = blockIdx.x * 32 + pos;
    const int b   = m >> 12;
    const int hw  = m & 4095;
    const int ho  = hw >> 6, wo = hw & 63;
    const char* xTb = (const char*)g_xT + ((size_t)b << 22);
    uint16_t* dA = g_Af + (size_t)m * KTOT;

    #pragma unroll 1
    for (int tap = 0; tap < KTAPS; ++tap) {
        const float offy = off[((b * 18 + 2 * tap)     << 12) + hw];
        const float offx = off[((b * 18 + 2 * tap + 1) << 12) + hw];
        const float py = (float)(ho - 1 + tap / 3) + offy;
        const float px = (float)(wo - 1 + tap % 3) + offx;
        const float y0f = floorf(py), x0f = floorf(px);
        const int y0 = (int)y0f, x0 = (int)x0f;
        const float fy = py - y0f, fx = px - x0f;
        float w00 = (1.f - fy) * (1.f - fx), w01 = (1.f - fy) * fx;
        float w10 = fy * (1.f - fx),         w11 = fy * fx;
        const bool vy0 = (unsigned)y0 < 64u, vy1 = (unsigned)(y0 + 1) < 64u;
        const bool vx0 = (unsigned)x0 < 64u, vx1 = (unsigned)(x0 + 1) < 64u;
        if (!(vy0 && vx0)) w00 = 0.f;
        if (!(vy0 && vx1)) w01 = 0.f;
        if (!(vy1 && vx0)) w10 = 0.f;
        if (!(vy1 && vx1)) w11 = 0.f;
        const int cy0 = min(max(y0, 0), 63), cy1 = min(max(y0 + 1, 0), 63);
        const int cx0 = min(max(x0, 0), 63), cx1 = min(max(x0 + 1, 0), 63);
        const int o00 = (cy0 * 64 + cx0) << 10, o01 = (cy0 * 64 + cx1) << 10;
        const int o10 = (cy1 * 64 + cx0) << 10, o11 = (cy1 * 64 + cx1) << 10;

        #pragma unroll
        for (int j = 0; j < 8; ++j) {
            const int co = j * 128 + sub * 16;
            const float4 a0 = *(const float4*)(xTb + o00 + co);
            const float4 a1 = *(const float4*)(xTb + o01 + co);
            const float4 a2 = *(const float4*)(xTb + o10 + co);
            const float4 a3 = *(const float4*)(xTb + o11 + co);
            float4 v;
            v.x = w00*a0.x + w01*a1.x + w10*a2.x + w11*a3.x;
            v.y = w00*a0.y + w01*a1.y + w10*a2.y + w11*a3.y;
            v.z = w00*a0.z + w01*a1.z + w10*a2.z + w11*a3.z;
            v.w = w00*a0.w + w01*a1.w + w10*a2.w + w11*a3.w;
            __half2 h0 = __floats2half2_rn(v.x, v.y);
            __half2 h1 = __floats2half2_rn(v.z, v.w);
            const int ko = tap * 256 + j * 32 + sub * 4;
            *(uint2*)(dA + ko) = make_uint2(*(uint32_t*)&h0, *(uint32_t*)&h1);
        }
    }
}

// ---------------- asm helpers ----------------
__device__ __forceinline__ uint32_t smem_u32(const void* p) {
    uint32_t a;
    asm("{ .reg .u64 t; cvta.to.shared.u64 t, %1; cvt.u32.u64 %0, t; }"
        : "=r"(a) : "l"(p));
    return a;
}
__device__ __forceinline__ void ldsm4(uint32_t* r, uint32_t a) {
    asm volatile("ldmatrix.sync.aligned.m8n8.x4.shared.b16 {%0,%1,%2,%3}, [%4];"
                 : "=r"(r[0]), "=r"(r[1]), "=r"(r[2]), "=r"(r[3]) : "r"(a));
}
__device__ __forceinline__ void hmma(float* d, const uint32_t* a,
                                     uint32_t b0, uint32_t b1) {
    asm volatile(
        "mma.sync.aligned.m16n8k16.row.col.f32.f16.f16.f32 "
        "{%0,%1,%2,%3}, {%4,%5,%6,%7}, {%8,%9}, {%0,%1,%2,%3};"
        : "+f"(d[0]), "+f"(d[1]), "+f"(d[2]), "+f"(d[3])
        : "r"(a[0]), "r"(a[1]), "r"(a[2]), "r"(a[3]), "r"(b0), "r"(b1));
}
__device__ __forceinline__ void cpasync16(uint32_t dst, const void* src) {
    asm volatile("cp.async.cg.shared.global [%0], [%1], 16;"
                 :: "r"(dst), "l"(src) : "memory");
}

// ------ dense GEMM, 1-term fp16, 128-thr CTAs, 4 CTAs/SM, 2-stage --------
__global__ __launch_bounds__(NTHREADS, 4)
void gemm(const float* __restrict__ bias, float* __restrict__ out)
{
    extern __shared__ char smem[];
    const uint32_t sbase = smem_u32(smem);
    const int tid = threadIdx.x;
    const int wid = tid >> 5;
    const int lid = tid & 31;

    const int mtile = blockIdx.x * BM;
    const int ntile = blockIdx.y * BN;
    const int b   = mtile >> 12;
    const int hw0 = mtile & 4095;

    // 4 warps, warp tile M64 x N32 (all warps share full BM)
    const int ncol = wid * 32;
    const uint32_t aoff = (uint32_t)(lid & 15) * PITCH + (uint32_t)(lid >> 4) * 16;
    const uint32_t boff = (uint32_t)(lid & 7) * PITCH
                        + (uint32_t)((lid >> 3) & 1) * 16
                        + (uint32_t)(lid >> 4) * (8 * PITCH);

    float acc[4][4][4];
    #pragma unroll
    for (int i = 0; i < 4; ++i)
        #pragma unroll
        for (int j = 0; j < 4; ++j)
            #pragma unroll
            for (int k = 0; k < 4; ++k) acc[i][j][k] = 0.f;

    auto fill = [&](int chunk, int st) {
        const int ke = chunk * BK;
        const uint32_t base = sbase + st * STAGE;
        // A: 512 x 16B -> 4 per thread
        #pragma unroll
        for (int i = 0; i < 4; ++i) {
            const int id = tid + (i << 7);
            const int row = id >> 3, s = id & 7;
            const uint32_t d = (uint32_t)(row * PITCH + s * 16);
            cpasync16(base + GA + d,
                      g_Af + (size_t)(mtile + row) * KTOT + ke + s * 8);
        }
        // B: 1024 x 16B -> 8 per thread
        #pragma unroll
        for (int i = 0; i < 8; ++i) {
            const int id = tid + (i << 7);
            const int n = id >> 3, s = id & 7;
            const uint32_t d = (uint32_t)(n * PITCH + s * 16);
            cpasync16(base + GB + d,
                      g_wBf + (size_t)(ntile + n) * KTOT + ke + s * 8);
        }
        asm volatile("cp.async.commit_group;" ::: "memory");
    };

    auto do_mma = [&](int st) {
        const uint32_t base = sbase + st * STAGE;
        const uint32_t sA = base + GA + aoff;
        const uint32_t sB = base + GB + ncol * PITCH + boff;
        #pragma unroll
        for (int ks = 0; ks < 4; ++ks) {
            const uint32_t ka = ks * 32;
            uint32_t b4[2][4];
            ldsm4(b4[0], sB + ka);
            ldsm4(b4[1], sB + 16 * PITCH + ka);
            uint32_t a4[4][4];
            #pragma unroll
            for (int ms = 0; ms < 4; ++ms)
                ldsm4(a4[ms], sA + ms * (16 * PITCH) + ka);
            #pragma unroll
            for (int np = 0; np < 2; ++np)
                #pragma unroll
                for (int ms = 0; ms < 4; ++ms) {
                    hmma(acc[ms][np * 2],     a4[ms], b4[np][0], b4[np][1]);
                    hmma(acc[ms][np * 2 + 1], a4[ms], b4[np][2], b4[np][3]);
                }
        }
    };

    // ---- 2-stage pipeline ----
    fill(0, 0);
    asm volatile("cp.async.wait_group 0;" ::: "memory");
    __syncthreads();

    #pragma unroll 1
    for (int chunk = 0; chunk < NCHUNK; ++chunk) {
        const int st = chunk & 1;
        if (chunk + 1 < NCHUNK) fill(chunk + 1, st ^ 1);
        do_mma(st);
        asm volatile("cp.async.wait_group 0;" ::: "memory");
        __syncthreads();
    }

    // ---- epilogue: transpose through smem, coalesced stores ----
    float* csf = (float*)smem;
    const int g  = lid >> 2;
    const int t2 = (lid & 3) * 2;
    const int outbase = (b << 20) + hw0;
    #pragma unroll 1
    for (int p = 0; p < 4; ++p) {
        if (wid == p) {
            #pragma unroll
            for (int j = 0; j < 4; ++j) {
                const int nl = j * 8 + t2;
                #pragma unroll
                for (int ms = 0; ms < 4; ++ms) {
                    const float* a4 = acc[ms][j];
                    const int m = ms * 16 + g;
                    csf[nl * CS_PITCH + m]           = a4[0];
                    csf[(nl + 1) * CS_PITCH + m]     = a4[1];
                    csf[nl * CS_PITCH + m + 8]       = a4[2];
                    csf[(nl + 1) * CS_PITCH + m + 8] = a4[3];
                }
            }
        }
        __syncthreads();
        #pragma unroll
        for (int it = 0; it < 16; ++it) {
            const int e = tid + it * NTHREADS;
            const int mm = e & 63;
            const int nn = e >> 6;          // 0..31
            const int n = ntile + p * 32 + nn;
            out[outbase + (n << 12) + mm] = csf[nn * CS_PITCH + mm] + __ldg(bias + n);
        }
        __syncthreads();
    }
}

extern "C" void kernel_launch(void* const* d_in, const int* in_sizes, int n_in,
                              void* d_out, int out_size)
{
    const float* x    = (const float*)d_in[0];
    const float* off  = (const float*)d_in[1];
    const float* w    = (const float*)d_in[2];
    const float* bias = (const float*)d_in[3];
    float* out        = (float*)d_out;

    cudaFuncSetAttribute(gemm, cudaFuncAttributeMaxDynamicSharedMemorySize, GSMEM);

    transpose_x<<<dim3(HW / 32, C_IN / 32, 4), dim3(32, 8)>>>(x);
    prep_w<<<(C_OUT * KTOT) / 256, 256>>>(w);
    im2col_f16<<<MTOT / 32, 256>>>(off);
    gemm<<<dim3(MTOT / BM, C_OUT / BN), NTHREADS, GSMEM>>>(bias, out);
}

// round 15
// speedup vs baseline: 1.3864x; 1.3864x over previous
#include <cuda_runtime.h>
#include <cuda_fp16.h>
#include <cstdint>

// ---------------- problem constants ----------------
#define C_IN   256
#define C_OUT  256
#define HW     4096
#define KTAPS  9
#define KTOT   2304          // tap-major: kord = tap*256 + c
#define MTOT   16384

// ---------------- GEMM tiling ----------------
#define BMC 256              // CTA m rows (2 subtiles of 128)
#define BM  128              // subtile
#define BN  128
#define BK  64
#define NSUB 2
#define TOTCH (NSUB * 36)    // 72 chunks per CTA
#define NTH   640            // 512 consumers + 128 producers
#define NCONS 512

#define PITCH 144            // 64 k * 2B + 16B pad (conflict-free)
#define ABUF  (BM * PITCH)   // 18432
#define BBUF  (BN * PITCH)   // 18432
#define STAGE (ABUF + BBUF)  // 36864
#define NSTAGE 4
#define GA 0
#define GB ABUF
#define CS_OFF (NSTAGE * STAGE)          // 147456
#define CS_PITCH 129
#define GSMEM (CS_OFF + 32 * CS_PITCH * 4)   // 163968

// ---------------- device scratch ----------------
__device__ float    g_xT[4 * HW * C_IN];                  // NHWC, 16MB
__device__ __align__(16) uint16_t g_wBf[C_OUT * KTOT];    // fp16, [o][kord]
__device__ __align__(16) uint16_t g_Af[(size_t)MTOT * KTOT];  // im2col fp16

// ---------------- prep kernels ----------------
__global__ void prep_w(const float* __restrict__ w) {
    int i = blockIdx.x * 256 + threadIdx.x;
    int kord = i % KTOT;
    int o    = i / KTOT;
    int tap  = kord >> 8;
    int c    = kord & 255;
    __half h = __float2half_rn(w[o * KTOT + c * KTAPS + tap]);
    g_wBf[i] = *(uint16_t*)&h;
}

__global__ void transpose_x(const float* __restrict__ x) {
    __shared__ float t[32][33];
    const int b   = blockIdx.z;
    const int hw0 = blockIdx.x * 32;
    const int c0  = blockIdx.y * 32;
    const int tx  = threadIdx.x, ty = threadIdx.y;
    #pragma unroll
    for (int i = 0; i < 4; ++i)
        t[ty + i * 8][tx] = x[((b * C_IN + c0 + ty + i * 8) << 12) + hw0 + tx];
    __syncthreads();
    #pragma unroll
    for (int i = 0; i < 4; ++i)
        g_xT[b * (HW * C_IN) + (hw0 + ty + i * 8) * C_IN + c0 + tx] =
            t[tx][ty + i * 8];
}

// ---------------- im2col -> single fp16 (no smem, no syncs) ----------------
__global__ __launch_bounds__(256)
void im2col_f16(const float* __restrict__ off)
{
    const int tid = threadIdx.x;
    const int pos = tid >> 3;
    const int sub = tid & 7;
    const int m   = blockIdx.x * 32 + pos;
    const int b   = m >> 12;
    const int hw  = m & 4095;
    const int ho  = hw >> 6, wo = hw & 63;
    const char* xTb = (const char*)g_xT + ((size_t)b << 22);
    uint16_t* dA = g_Af + (size_t)m * KTOT;

    #pragma unroll 1
    for (int tap = 0; tap < KTAPS; ++tap) {
        const float offy = off[((b * 18 + 2 * tap)     << 12) + hw];
        const float offx = off[((b * 18 + 2 * tap + 1) << 12) + hw];
        const float py = (float)(ho - 1 + tap / 3) + offy;
        const float px = (float)(wo - 1 + tap % 3) + offx;
        const float y0f = floorf(py), x0f = floorf(px);
        const int y0 = (int)y0f, x0 = (int)x0f;
        const float fy = py - y0f, fx = px - x0f;
        float w00 = (1.f - fy) * (1.f - fx), w01 = (1.f - fy) * fx;
        float w10 = fy * (1.f - fx),         w11 = fy * fx;
        const bool vy0 = (unsigned)y0 < 64u, vy1 = (unsigned)(y0 + 1) < 64u;
        const bool vx0 = (unsigned)x0 < 64u, vx1 = (unsigned)(x0 + 1) < 64u;
        if (!(vy0 && vx0)) w00 = 0.f;
        if (!(vy0 && vx1)) w01 = 0.f;
        if (!(vy1 && vx0)) w10 = 0.f;
        if (!(vy1 && vx1)) w11 = 0.f;
        const int cy0 = min(max(y0, 0), 63), cy1 = min(max(y0 + 1, 0), 63);
        const int cx0 = min(max(x0, 0), 63), cx1 = min(max(x0 + 1, 0), 63);
        const int o00 = (cy0 * 64 + cx0) << 10, o01 = (cy0 * 64 + cx1) << 10;
        const int o10 = (cy1 * 64 + cx0) << 10, o11 = (cy1 * 64 + cx1) << 10;

        #pragma unroll
        for (int j = 0; j < 8; ++j) {
            const int co = j * 128 + sub * 16;
            const float4 a0 = *(const float4*)(xTb + o00 + co);
            const float4 a1 = *(const float4*)(xTb + o01 + co);
            const float4 a2 = *(const float4*)(xTb + o10 + co);
            const float4 a3 = *(const float4*)(xTb + o11 + co);
            float4 v;
            v.x = w00*a0.x + w01*a1.x + w10*a2.x + w11*a3.x;
            v.y = w00*a0.y + w01*a1.y + w10*a2.y + w11*a3.y;
            v.z = w00*a0.z + w01*a1.z + w10*a2.z + w11*a3.z;
            v.w = w00*a0.w + w01*a1.w + w10*a2.w + w11*a3.w;
            __half2 h0 = __floats2half2_rn(v.x, v.y);
            __half2 h1 = __floats2half2_rn(v.z, v.w);
            const int ko = tap * 256 + j * 32 + sub * 4;
            *(uint2*)(dA + ko) = make_uint2(*(uint32_t*)&h0, *(uint32_t*)&h1);
        }
    }
}

// ---------------- asm helpers ----------------
__device__ __forceinline__ uint32_t smem_u32(const void* p) {
    uint32_t a;
    asm("{ .reg .u64 t; cvta.to.shared.u64 t, %1; cvt.u32.u64 %0, t; }"
        : "=r"(a) : "l"(p));
    return a;
}
__device__ __forceinline__ void ldsm4(uint32_t* r, uint32_t a) {
    asm volatile("ldmatrix.sync.aligned.m8n8.x4.shared.b16 {%0,%1,%2,%3}, [%4];"
                 : "=r"(r[0]), "=r"(r[1]), "=r"(r[2]), "=r"(r[3]) : "r"(a));
}
__device__ __forceinline__ void hmma(float* d, const uint32_t* a,
                                     uint32_t b0, uint32_t b1) {
    asm volatile(
        "mma.sync.aligned.m16n8k16.row.col.f32.f16.f16.f32 "
        "{%0,%1,%2,%3}, {%4,%5,%6,%7}, {%8,%9}, {%0,%1,%2,%3};"
        : "+f"(d[0]), "+f"(d[1]), "+f"(d[2]), "+f"(d[3])
        : "r"(a[0]), "r"(a[1]), "r"(a[2]), "r"(a[3]), "r"(b0), "r"(b1));
}
__device__ __forceinline__ void cpasync16(uint32_t dst, const void* src) {
    asm volatile("cp.async.cg.shared.global [%0], [%1], 16;"
                 :: "r"(dst), "l"(src) : "memory");
}
__device__ __forceinline__ void bar_sync(int id, int cnt) {
    asm volatile("bar.sync %0, %1;" :: "r"(id), "r"(cnt) : "memory");
}
__device__ __forceinline__ void bar_arrive(int id, int cnt) {
    asm volatile("bar.arrive %0, %1;" :: "r"(id), "r"(cnt) : "memory");
}
// barrier ids: full[s] = 1+s, empty[s] = 5+s, consumer-epilogue = 9

// ---- warp-specialized GEMM: 4 producer warps + 16 consumer warps ----------
__global__ __launch_bounds__(NTH, 1)
void gemm(const float* __restrict__ bias, float* __restrict__ out)
{
    extern __shared__ char smem[];
    const uint32_t sbase = smem_u32(smem);
    const int tid = threadIdx.x;
    const int mtile = blockIdx.x * BMC;
    const int ntile = blockIdx.y * BN;
    const int b = mtile >> 12;

    if (tid >= NCONS) {
        // ================= PRODUCER (128 threads) =================
        const int pt = tid - NCONS;
        #pragma unroll 1
        for (int c = 0; c < TOTCH; ++c) {
            const int st = c & 3;
            if (c >= NSTAGE) bar_sync(5 + st, NTH);          // stage empty
            const int sub = c / 36;
            const int ke  = (c % 36) * BK;
            const uint32_t base = sbase + st * STAGE;
            #pragma unroll
            for (int i = 0; i < 8; ++i) {
                const int id = pt + (i << 7);                // 0..1023
                const int row = id >> 3, s = id & 7;
                const uint32_t d = (uint32_t)(row * PITCH + s * 16);
                cpasync16(base + GA + d,
                          g_Af + (size_t)(mtile + sub * BM + row) * KTOT + ke + s * 8);
                cpasync16(base + GB + d,
                          g_wBf + (size_t)(ntile + row) * KTOT + ke + s * 8);
            }
            asm volatile("cp.async.commit_group;" ::: "memory");
            if (c >= 3) {
                asm volatile("cp.async.wait_group 3;" ::: "memory");
                bar_arrive(1 + ((c - 3) & 3), NTH);          // stage full
            }
        }
        asm volatile("cp.async.wait_group 2;" ::: "memory");
        bar_arrive(1 + ((TOTCH - 3) & 3), NTH);
        asm volatile("cp.async.wait_group 1;" ::: "memory");
        bar_arrive(1 + ((TOTCH - 2) & 3), NTH);
        asm volatile("cp.async.wait_group 0;" ::: "memory");
        bar_arrive(1 + ((TOTCH - 1) & 3), NTH);
    } else {
        // ================= CONSUMER (512 threads, 16 warps) =================
        const int wid = tid >> 5;
        const int lid = tid & 31;
        const int wm = wid & 3, wn = wid >> 2;
        const int mrow = wm * 32;
        const int ncol = wn * 32;
        const uint32_t aoff = (uint32_t)(lid & 15) * PITCH + (uint32_t)(lid >> 4) * 16;
        const uint32_t boff = (uint32_t)(lid & 7) * PITCH
                            + (uint32_t)((lid >> 3) & 1) * 16
                            + (uint32_t)(lid >> 4) * (8 * PITCH);
        float* csf = (float*)(smem + CS_OFF);
        const int g  = lid >> 2;
        const int t2 = (lid & 3) * 2;

        float acc[2][4][4];
        #pragma unroll
        for (int i = 0; i < 2; ++i)
            #pragma unroll
            for (int j = 0; j < 4; ++j)
                #pragma unroll
                for (int k = 0; k < 4; ++k) acc[i][j][k] = 0.f;

        #pragma unroll 1
        for (int c = 0; c < TOTCH; ++c) {
            const int st = c & 3;
            bar_sync(1 + st, NTH);                           // stage full
            const uint32_t base = sbase + st * STAGE;
            const uint32_t sA = base + GA + mrow * PITCH + aoff;
            const uint32_t sB = base + GB + ncol * PITCH + boff;
            #pragma unroll
            for (int ks = 0; ks < 4; ++ks) {
                const uint32_t ka = ks * 32;
                uint32_t a0[4], a1[4], b0[4], b1[4];
                ldsm4(a0, sA + ka);
                ldsm4(a1, sA + 16 * PITCH + ka);
                ldsm4(b0, sB + ka);
                ldsm4(b1, sB + 16 * PITCH + ka);
                hmma(acc[0][0], a0, b0[0], b0[1]);
                hmma(acc[0][1], a0, b0[2], b0[3]);
                hmma(acc[0][2], a0, b1[0], b1[1]);
                hmma(acc[0][3], a0, b1[2], b1[3]);
                hmma(acc[1][0], a1, b0[0], b0[1]);
                hmma(acc[1][1], a1, b0[2], b0[3]);
                hmma(acc[1][2], a1, b1[0], b1[1]);
                hmma(acc[1][3], a1, b1[2], b1[3]);
            }
            bar_arrive(5 + st, NTH);                         // stage empty

            if ((c % 36) == 35) {
                // ---- epilogue for finished subtile (producers keep running) ----
                const int sub = c / 36;
                const int hw0 = (mtile & 4095) + sub * BM;
                const int outbase = (b << 20) + hw0;
                #pragma unroll 1
                for (int p = 0; p < 4; ++p) {
                    if (wn == p) {
                        #pragma unroll
                        for (int j = 0; j < 4; ++j) {
                            const int nl = j * 8 + t2;
                            #pragma unroll
                            for (int mf = 0; mf < 2; ++mf) {
                                const float* a4 = acc[mf][j];
                                const int m = mrow + mf * 16 + g;
                                csf[nl * CS_PITCH + m]           = a4[0];
                                csf[(nl + 1) * CS_PITCH + m]     = a4[1];
                                csf[nl * CS_PITCH + m + 8]       = a4[2];
                                csf[(nl + 1) * CS_PITCH + m + 8] = a4[3];
                            }
                        }
                    }
                    bar_sync(9, NCONS);
                    #pragma unroll
                    for (int it = 0; it < 8; ++it) {
                        const int e = tid + it * NCONS;
                        const int mm = e & 127;
                        const int nn = e >> 7;               // 0..31
                        const int n = ntile + p * 32 + nn;
                        out[outbase + (n << 12) + mm] =
                            csf[nn * CS_PITCH + mm] + __ldg(bias + n);
                    }
                    bar_sync(9, NCONS);
                }
                #pragma unroll
                for (int i = 0; i < 2; ++i)
                    #pragma unroll
                    for (int j = 0; j < 4; ++j)
                        #pragma unroll
                        for (int k = 0; k < 4; ++k) acc[i][j][k] = 0.f;
            }
        }
    }
}

extern "C" void kernel_launch(void* const* d_in, const int* in_sizes, int n_in,
                              void* d_out, int out_size)
{
    const float* x    = (const float*)d_in[0];
    const float* off  = (const float*)d_in[1];
    const float* w    = (const float*)d_in[2];
    const float* bias = (const float*)d_in[3];
    float* out        = (float*)d_out;

    cudaFuncSetAttribute(gemm, cudaFuncAttributeMaxDynamicSharedMemorySize, GSMEM);

    transpose_x<<<dim3(HW / 32, C_IN / 32, 4), dim3(32, 8)>>>(x);
    prep_w<<<(C_OUT * KTOT) / 256, 256>>>(w);
    im2col_f16<<<MTOT / 32, 256>>>(off);
    gemm<<<dim3(MTOT / BMC, C_OUT / BN), NTH, GSMEM>>>(bias, out);
}